// round 4
// baseline (speedup 1.0000x reference)
#include <cuda_runtime.h>

#define MAXNB 1184

// Device-global scratch (no allocations allowed).
static __device__ double g_part[MAXNB][9];  // per-block partials: S0,S1,S2,P00,P11,P22,P01,P02,P12
static __device__ float  g_par[12];         // basis rows (right,up,fwd) row-major [9], refPos [3]

// Pass 1: 9 reductions over rows 0..2 -> per-block partials (no atomics).
__global__ void __launch_bounds__(256) k_reduce(const float* __restrict__ x, int T) {
    const int nv = T >> 2;
    const size_t Ts = (size_t)T;
    const float4* __restrict__ x0 = (const float4*)(x);
    const float4* __restrict__ x1 = (const float4*)(x + Ts);
    const float4* __restrict__ x2 = (const float4*)(x + 2 * Ts);

    float acc[9];
#pragma unroll
    for (int k = 0; k < 9; ++k) acc[k] = 0.0f;

    const int gid = blockIdx.x * blockDim.x + threadIdx.x;
    const int stride = gridDim.x * blockDim.x;

    for (int i = gid; i < nv; i += stride) {
        float4 v0 = x0[i], v1 = x1[i], v2 = x2[i];
        float c0[4] = {v0.x, v0.y, v0.z, v0.w};
        float c1[4] = {v1.x, v1.y, v1.z, v1.w};
        float c2[4] = {v2.x, v2.y, v2.z, v2.w};
#pragma unroll
        for (int k = 0; k < 4; ++k) {
            float a = c0[k], b = c1[k], c = c2[k];
            acc[0] += a;     acc[1] += b;     acc[2] += c;
            acc[3] += a * a; acc[4] += b * b; acc[5] += c * c;
            acc[6] += a * b; acc[7] += a * c; acc[8] += b * c;
        }
    }
    // Scalar tail (T % 4 != 0 safety; T=4M is divisible).
    for (int t = (nv << 2) + gid; t < T; t += stride) {
        float a = x[t], b = x[Ts + t], c = x[2 * Ts + t];
        acc[0] += a;     acc[1] += b;     acc[2] += c;
        acc[3] += a * a; acc[4] += b * b; acc[5] += c * c;
        acc[6] += a * b; acc[7] += a * c; acc[8] += b * c;
    }

    // Warp reduce fp32 (partials are tiny: ~16 columns/thread).
#pragma unroll
    for (int k = 0; k < 9; ++k) {
        float v = acc[k];
#pragma unroll
        for (int off = 16; off > 0; off >>= 1)
            v += __shfl_down_sync(0xffffffffu, v, off);
        acc[k] = v;
    }
    __shared__ float ws[9][8];
    const int lane = threadIdx.x & 31, warp = threadIdx.x >> 5;
    if (lane == 0) {
#pragma unroll
        for (int k = 0; k < 9; ++k) ws[k][warp] = acc[k];
    }
    __syncthreads();
    if (threadIdx.x == 0) {
#pragma unroll
        for (int k = 0; k < 9; ++k) {
            double d = 0.0;
#pragma unroll
            for (int w = 0; w < 8; ++w) d += (double)ws[k][w];
            g_part[blockIdx.x][k] = d;   // plain store, no atomic
        }
    }
}

// Pass 2: block 0 = final reduce + eigensolve (serial FP64 hidden under copy);
//         blocks 1.. = stream rows 7..9 -> out rows 3..5.
__global__ void __launch_bounds__(256) k_mid(const float* __restrict__ x,
                                             const float* __restrict__ ra,
                                             float* __restrict__ out, int T, int NB) {
    const size_t Ts = (size_t)T;

    if (blockIdx.x == 0) {
        // ---- parallel final reduce of g_part[0..NB-1][9] ----
        double acc[9];
#pragma unroll
        for (int k = 0; k < 9; ++k) acc[k] = 0.0;
        for (int i = threadIdx.x; i < NB; i += blockDim.x) {
#pragma unroll
            for (int k = 0; k < 9; ++k) acc[k] += g_part[i][k];
        }
#pragma unroll
        for (int k = 0; k < 9; ++k) {
            double v = acc[k];
#pragma unroll
            for (int off = 16; off > 0; off >>= 1)
                v += __shfl_down_sync(0xffffffffu, v, off);
            acc[k] = v;
        }
        __shared__ double ws[9][8];
        const int lane = threadIdx.x & 31, warp = threadIdx.x >> 5;
        if (lane == 0) {
#pragma unroll
            for (int k = 0; k < 9; ++k) ws[k][warp] = acc[k];
        }
        __syncthreads();
        if (threadIdx.x != 0) return;

        double S[9];
#pragma unroll
        for (int k = 0; k < 9; ++k) {
            double d = 0.0;
#pragma unroll
            for (int w = 0; w < 8; ++w) d += ws[k][w];
            S[k] = d;
        }

        // ---- covariance -> Jacobi (double) -> basis ----
        const double Tn = (double)T;
        double A[3][3];
        A[0][0] = (S[3] - S[0] * S[0] / Tn) / (Tn - 1.0);
        A[1][1] = (S[4] - S[1] * S[1] / Tn) / (Tn - 1.0);
        A[2][2] = (S[5] - S[2] * S[2] / Tn) / (Tn - 1.0);
        A[0][1] = A[1][0] = (S[6] - S[0] * S[1] / Tn) / (Tn - 1.0);
        A[0][2] = A[2][0] = (S[7] - S[0] * S[2] / Tn) / (Tn - 1.0);
        A[1][2] = A[2][1] = (S[8] - S[1] * S[2] / Tn) / (Tn - 1.0);

        const double scale = fabs(A[0][0]) + fabs(A[1][1]) + fabs(A[2][2]) + 1e-300;
        double V[3][3] = {{1, 0, 0}, {0, 1, 0}, {0, 0, 1}};
        for (int sweep = 0; sweep < 8; ++sweep) {
            double off = fabs(A[0][1]) + fabs(A[0][2]) + fabs(A[1][2]);
            if (off < 1e-14 * scale) break;
            for (int p = 0; p < 2; ++p) {
                for (int q = p + 1; q < 3; ++q) {
                    double apq = A[p][q];
                    if (fabs(apq) < 1e-200) continue;
                    double theta = (A[q][q] - A[p][p]) / (2.0 * apq);
                    double t = 1.0 / (fabs(theta) + sqrt(theta * theta + 1.0));
                    if (theta < 0.0) t = -t;
                    double c = 1.0 / sqrt(t * t + 1.0);
                    double s = t * c;
                    double app = A[p][p], aqq = A[q][q];
                    A[p][p] = app - t * apq;
                    A[q][q] = aqq + t * apq;
                    A[p][q] = A[q][p] = 0.0;
                    int r = 3 - p - q;
                    double arp = A[r][p], arq = A[r][q];
                    A[r][p] = A[p][r] = c * arp - s * arq;
                    A[r][q] = A[q][r] = s * arp + c * arq;
                    for (int i = 0; i < 3; ++i) {
                        double vip = V[i][p], viq = V[i][q];
                        V[i][p] = c * vip - s * viq;
                        V[i][q] = s * vip + c * viq;
                    }
                }
            }
        }
        int m = 0;
        if (A[1][1] > A[m][m]) m = 1;
        if (A[2][2] > A[m][m]) m = 2;
        double vz0 = V[0][m], vz1 = V[1][m], vz2 = V[2][m];

        // ZFwd = quat-rotate (0,0,1) with q = x[3..6][t=0]
        double qx = (double)x[3 * Ts], qy = (double)x[4 * Ts];
        double qz = (double)x[5 * Ts], qw = (double)x[6 * Ts];
        double zfx = 2.0 * (qx * qz + qw * qy);
        double zfy = 2.0 * (qy * qz - qw * qx);
        double zfz = 1.0 - 2.0 * (qx * qx + qy * qy);
        if (zfx * vz0 + zfy * vz1 + zfz * vz2 < 0.0) { vz0 = -vz0; vz1 = -vz1; vz2 = -vz2; }

        double ux = (double)ra[0], uy = (double)ra[1], uz = (double)ra[2];
        double rx = uy * vz2 - uz * vz1;            // right = up x pca_z
        double ry = uz * vz0 - ux * vz2;
        double rz = ux * vz1 - uy * vz0;
        double fx = ry * uz - rz * uy;              // fwd = right x up
        double fy = rz * ux - rx * uz;
        double fz = rx * uy - ry * ux;

        g_par[0] = (float)rx; g_par[1] = (float)ry; g_par[2] = (float)rz;
        g_par[3] = (float)ux; g_par[4] = (float)uy; g_par[5] = (float)uz;
        g_par[6] = (float)fx; g_par[7] = (float)fy; g_par[8] = (float)fz;
        g_par[9]  = x[0];
        g_par[10] = x[Ts];
        g_par[11] = x[2 * Ts];
        return;
    }

    // ---- copy rows 7..9 -> out rows 3..5 (hides the eigensolve) ----
    const int nv = T >> 2;
    const float4* __restrict__ a0 = (const float4*)(x + 7 * Ts);
    const float4* __restrict__ a1 = (const float4*)(x + 8 * Ts);
    const float4* __restrict__ a2 = (const float4*)(x + 9 * Ts);
    float4* __restrict__ o3 = (float4*)(out + 3 * Ts);
    float4* __restrict__ o4 = (float4*)(out + 4 * Ts);
    float4* __restrict__ o5 = (float4*)(out + 5 * Ts);

    const int gid = (blockIdx.x - 1) * blockDim.x + threadIdx.x;
    const int stride = (gridDim.x - 1) * blockDim.x;
    for (int i = gid; i < nv; i += stride) {
        o3[i] = a0[i];
        o4[i] = a1[i];
        o5[i] = a2[i];
    }
    for (int t = (nv << 2) + gid; t < T; t += stride) {
        out[3 * Ts + t] = x[7 * Ts + t];
        out[4 * Ts + t] = x[8 * Ts + t];
        out[5 * Ts + t] = x[9 * Ts + t];
    }
}

// Pass 3: out rows 0..2 = basis * (Xpos - refPos)
__global__ void __launch_bounds__(256) k_transform(const float* __restrict__ x,
                                                   float* __restrict__ out, int T) {
    const int nv = T >> 2;
    const size_t Ts = (size_t)T;
    const float b00 = g_par[0], b01 = g_par[1], b02 = g_par[2];
    const float b10 = g_par[3], b11 = g_par[4], b12 = g_par[5];
    const float b20 = g_par[6], b21 = g_par[7], b22 = g_par[8];
    const float r0 = g_par[9], r1 = g_par[10], r2 = g_par[11];

    const float4* __restrict__ x0 = (const float4*)(x);
    const float4* __restrict__ x1 = (const float4*)(x + Ts);
    const float4* __restrict__ x2 = (const float4*)(x + 2 * Ts);
    float4* __restrict__ o0 = (float4*)(out);
    float4* __restrict__ o1 = (float4*)(out + Ts);
    float4* __restrict__ o2 = (float4*)(out + 2 * Ts);

    const int gid = blockIdx.x * blockDim.x + threadIdx.x;
    const int stride = gridDim.x * blockDim.x;

    for (int i = gid; i < nv; i += stride) {
        float4 v0 = x0[i], v1 = x1[i], v2 = x2[i];
        float c0[4] = {v0.x, v0.y, v0.z, v0.w};
        float c1[4] = {v1.x, v1.y, v1.z, v1.w};
        float c2[4] = {v2.x, v2.y, v2.z, v2.w};
        float w0[4], w1[4], w2[4];
#pragma unroll
        for (int k = 0; k < 4; ++k) {
            float d0 = c0[k] - r0, d1 = c1[k] - r1, d2 = c2[k] - r2;
            w0[k] = b00 * d0 + b01 * d1 + b02 * d2;
            w1[k] = b10 * d0 + b11 * d1 + b12 * d2;
            w2[k] = b20 * d0 + b21 * d1 + b22 * d2;
        }
        o0[i] = make_float4(w0[0], w0[1], w0[2], w0[3]);
        o1[i] = make_float4(w1[0], w1[1], w1[2], w1[3]);
        o2[i] = make_float4(w2[0], w2[1], w2[2], w2[3]);
    }
    for (int t = (nv << 2) + gid; t < T; t += stride) {
        float d0 = x[t] - r0, d1 = x[Ts + t] - r1, d2 = x[2 * Ts + t] - r2;
        out[t]          = b00 * d0 + b01 * d1 + b02 * d2;
        out[Ts + t]     = b10 * d0 + b11 * d1 + b12 * d2;
        out[2 * Ts + t] = b20 * d0 + b21 * d1 + b22 * d2;
    }
}

extern "C" void kernel_launch(void* const* d_in, const int* in_sizes, int n_in,
                              void* d_out, int out_size) {
    const float* x  = (const float*)d_in[0];
    const float* ra = (const float*)d_in[1];
    float* out = (float*)d_out;
    const int T = in_sizes[0] / 10;
    const int nv = T >> 2;

    int blocks = MAXNB;  // 148 SMs x 8
    int needed = (nv + 255) / 256;
    if (blocks > needed) blocks = needed;
    if (blocks < 1) blocks = 1;

    k_reduce<<<blocks, 256>>>(x, T);
    k_mid<<<blocks + 1, 256>>>(x, ra, out, T, blocks);
    k_transform<<<blocks, 256>>>(x, out, T);
}

// round 5
// speedup vs baseline: 1.1793x; 1.1793x over previous
#include <cuda_runtime.h>

#define RED_NB 888     // 6 blocks/SM x 148 SMs — one exact wave for k_reduce
#define CPY_NB 888     // copy blocks in k_mid (block 0 = solver, total 889 <= 1184 capacity)
#define TRF_NB 1184    // 8 blocks/SM x 148 SMs — one exact wave for k_transform

// Device-global scratch (no allocations allowed).
static __device__ double g_part[RED_NB][9];  // per-block partials: S0,S1,S2,P00,P11,P22,P01,P02,P12
static __device__ float  g_par[12];          // basis rows (right,up,fwd) row-major [9], refPos [3]

// Pass 1: 9 reductions over rows 0..2 -> per-block partials (no atomics).
// launch_bounds(256,6): cap regs at 42 so 6 blocks/SM always fit -> grid 888 = single wave.
__global__ void __launch_bounds__(256, 6) k_reduce(const float* __restrict__ x, int T) {
    const int nv = T >> 2;
    const size_t Ts = (size_t)T;
    const float4* __restrict__ x0 = (const float4*)(x);
    const float4* __restrict__ x1 = (const float4*)(x + Ts);
    const float4* __restrict__ x2 = (const float4*)(x + 2 * Ts);

    float acc[9];
#pragma unroll
    for (int k = 0; k < 9; ++k) acc[k] = 0.0f;

    const int gid = blockIdx.x * blockDim.x + threadIdx.x;
    const int stride = gridDim.x * blockDim.x;

    // Main loop: 2 index-chunks per iteration, all 6 loads issued before any math.
    int i = gid;
    for (; i + stride < nv; i += 2 * stride) {
        const int j = i + stride;
        float4 v0 = x0[i], v1 = x1[i], v2 = x2[i];
        float4 u0 = x0[j], u1 = x1[j], u2 = x2[j];
        float c0[8] = {v0.x, v0.y, v0.z, v0.w, u0.x, u0.y, u0.z, u0.w};
        float c1[8] = {v1.x, v1.y, v1.z, v1.w, u1.x, u1.y, u1.z, u1.w};
        float c2[8] = {v2.x, v2.y, v2.z, v2.w, u2.x, u2.y, u2.z, u2.w};
#pragma unroll
        for (int k = 0; k < 8; ++k) {
            float a = c0[k], b = c1[k], c = c2[k];
            acc[0] += a;     acc[1] += b;     acc[2] += c;
            acc[3] += a * a; acc[4] += b * b; acc[5] += c * c;
            acc[6] += a * b; acc[7] += a * c; acc[8] += b * c;
        }
    }
    for (; i < nv; i += stride) {
        float4 v0 = x0[i], v1 = x1[i], v2 = x2[i];
        float c0[4] = {v0.x, v0.y, v0.z, v0.w};
        float c1[4] = {v1.x, v1.y, v1.z, v1.w};
        float c2[4] = {v2.x, v2.y, v2.z, v2.w};
#pragma unroll
        for (int k = 0; k < 4; ++k) {
            float a = c0[k], b = c1[k], c = c2[k];
            acc[0] += a;     acc[1] += b;     acc[2] += c;
            acc[3] += a * a; acc[4] += b * b; acc[5] += c * c;
            acc[6] += a * b; acc[7] += a * c; acc[8] += b * c;
        }
    }
    // Scalar tail (T % 4 != 0 safety; T=4M is divisible).
    for (int t = (nv << 2) + gid; t < T; t += stride) {
        float a = x[t], b = x[Ts + t], c = x[2 * Ts + t];
        acc[0] += a;     acc[1] += b;     acc[2] += c;
        acc[3] += a * a; acc[4] += b * b; acc[5] += c * c;
        acc[6] += a * b; acc[7] += a * c; acc[8] += b * c;
    }

    // Warp reduce fp32 (partials are tiny: ~30 columns/thread).
#pragma unroll
    for (int k = 0; k < 9; ++k) {
        float v = acc[k];
#pragma unroll
        for (int off = 16; off > 0; off >>= 1)
            v += __shfl_down_sync(0xffffffffu, v, off);
        acc[k] = v;
    }
    __shared__ float ws[9][8];
    const int lane = threadIdx.x & 31, warp = threadIdx.x >> 5;
    if (lane == 0) {
#pragma unroll
        for (int k = 0; k < 9; ++k) ws[k][warp] = acc[k];
    }
    __syncthreads();
    // Parallel block tail: thread k (k<9) sums its statistic over the 8 warps.
    if (threadIdx.x < 9) {
        const int k = threadIdx.x;
        double d = 0.0;
#pragma unroll
        for (int w = 0; w < 8; ++w) d += (double)ws[k][w];
        g_part[blockIdx.x][k] = d;
    }
}

// Pass 2: block 0 = final reduce + eigensolve (serial FP64 hidden under copy);
//         blocks 1..CPY_NB = stream rows 7..9 -> out rows 3..5.
__global__ void __launch_bounds__(256, 8) k_mid(const float* __restrict__ x,
                                                const float* __restrict__ ra,
                                                float* __restrict__ out, int T) {
    const size_t Ts = (size_t)T;

    if (blockIdx.x == 0) {
        // ---- parallel final reduce of g_part[0..RED_NB-1][9] ----
        double acc[9];
#pragma unroll
        for (int k = 0; k < 9; ++k) acc[k] = 0.0;
        for (int i = threadIdx.x; i < RED_NB; i += blockDim.x) {
#pragma unroll
            for (int k = 0; k < 9; ++k) acc[k] += g_part[i][k];
        }
#pragma unroll
        for (int k = 0; k < 9; ++k) {
            double v = acc[k];
#pragma unroll
            for (int off = 16; off > 0; off >>= 1)
                v += __shfl_down_sync(0xffffffffu, v, off);
            acc[k] = v;
        }
        __shared__ double ws[9][8];
        const int lane = threadIdx.x & 31, warp = threadIdx.x >> 5;
        if (lane == 0) {
#pragma unroll
            for (int k = 0; k < 9; ++k) ws[k][warp] = acc[k];
        }
        __syncthreads();
        if (threadIdx.x != 0) return;

        double S[9];
#pragma unroll
        for (int k = 0; k < 9; ++k) {
            double d = 0.0;
#pragma unroll
            for (int w = 0; w < 8; ++w) d += ws[k][w];
            S[k] = d;
        }

        // ---- covariance -> Jacobi (double) -> basis ----
        const double Tn = (double)T;
        double A[3][3];
        A[0][0] = (S[3] - S[0] * S[0] / Tn) / (Tn - 1.0);
        A[1][1] = (S[4] - S[1] * S[1] / Tn) / (Tn - 1.0);
        A[2][2] = (S[5] - S[2] * S[2] / Tn) / (Tn - 1.0);
        A[0][1] = A[1][0] = (S[6] - S[0] * S[1] / Tn) / (Tn - 1.0);
        A[0][2] = A[2][0] = (S[7] - S[0] * S[2] / Tn) / (Tn - 1.0);
        A[1][2] = A[2][1] = (S[8] - S[1] * S[2] / Tn) / (Tn - 1.0);

        const double scale = fabs(A[0][0]) + fabs(A[1][1]) + fabs(A[2][2]) + 1e-300;
        double V[3][3] = {{1, 0, 0}, {0, 1, 0}, {0, 0, 1}};
        for (int sweep = 0; sweep < 8; ++sweep) {
            double off = fabs(A[0][1]) + fabs(A[0][2]) + fabs(A[1][2]);
            if (off < 1e-14 * scale) break;
            for (int p = 0; p < 2; ++p) {
                for (int q = p + 1; q < 3; ++q) {
                    double apq = A[p][q];
                    if (fabs(apq) < 1e-200) continue;
                    double theta = (A[q][q] - A[p][p]) / (2.0 * apq);
                    double t = 1.0 / (fabs(theta) + sqrt(theta * theta + 1.0));
                    if (theta < 0.0) t = -t;
                    double c = 1.0 / sqrt(t * t + 1.0);
                    double s = t * c;
                    double app = A[p][p], aqq = A[q][q];
                    A[p][p] = app - t * apq;
                    A[q][q] = aqq + t * apq;
                    A[p][q] = A[q][p] = 0.0;
                    int r = 3 - p - q;
                    double arp = A[r][p], arq = A[r][q];
                    A[r][p] = A[p][r] = c * arp - s * arq;
                    A[r][q] = A[q][r] = s * arp + c * arq;
                    for (int i = 0; i < 3; ++i) {
                        double vip = V[i][p], viq = V[i][q];
                        V[i][p] = c * vip - s * viq;
                        V[i][q] = s * vip + c * viq;
                    }
                }
            }
        }
        int m = 0;
        if (A[1][1] > A[m][m]) m = 1;
        if (A[2][2] > A[m][m]) m = 2;
        double vz0 = V[0][m], vz1 = V[1][m], vz2 = V[2][m];

        // ZFwd = quat-rotate (0,0,1) with q = x[3..6][t=0]
        double qx = (double)x[3 * Ts], qy = (double)x[4 * Ts];
        double qz = (double)x[5 * Ts], qw = (double)x[6 * Ts];
        double zfx = 2.0 * (qx * qz + qw * qy);
        double zfy = 2.0 * (qy * qz - qw * qx);
        double zfz = 1.0 - 2.0 * (qx * qx + qy * qy);
        if (zfx * vz0 + zfy * vz1 + zfz * vz2 < 0.0) { vz0 = -vz0; vz1 = -vz1; vz2 = -vz2; }

        double ux = (double)ra[0], uy = (double)ra[1], uz = (double)ra[2];
        double rx = uy * vz2 - uz * vz1;            // right = up x pca_z
        double ry = uz * vz0 - ux * vz2;
        double rz = ux * vz1 - uy * vz0;
        double fx = ry * uz - rz * uy;              // fwd = right x up
        double fy = rz * ux - rx * uz;
        double fz = rx * uy - ry * ux;

        g_par[0] = (float)rx; g_par[1] = (float)ry; g_par[2] = (float)rz;
        g_par[3] = (float)ux; g_par[4] = (float)uy; g_par[5] = (float)uz;
        g_par[6] = (float)fx; g_par[7] = (float)fy; g_par[8] = (float)fz;
        g_par[9]  = x[0];
        g_par[10] = x[Ts];
        g_par[11] = x[2 * Ts];
        return;
    }

    // ---- copy rows 7..9 -> out rows 3..5 (hides the eigensolve) ----
    const int nv = T >> 2;
    const float4* __restrict__ a0 = (const float4*)(x + 7 * Ts);
    const float4* __restrict__ a1 = (const float4*)(x + 8 * Ts);
    const float4* __restrict__ a2 = (const float4*)(x + 9 * Ts);
    float4* __restrict__ o3 = (float4*)(out + 3 * Ts);
    float4* __restrict__ o4 = (float4*)(out + 4 * Ts);
    float4* __restrict__ o5 = (float4*)(out + 5 * Ts);

    const int gid = (blockIdx.x - 1) * blockDim.x + threadIdx.x;
    const int stride = (gridDim.x - 1) * blockDim.x;
    for (int i = gid; i < nv; i += stride) {
        o3[i] = a0[i];
        o4[i] = a1[i];
        o5[i] = a2[i];
    }
    for (int t = (nv << 2) + gid; t < T; t += stride) {
        out[3 * Ts + t] = x[7 * Ts + t];
        out[4 * Ts + t] = x[8 * Ts + t];
        out[5 * Ts + t] = x[9 * Ts + t];
    }
}

// Pass 3: out rows 0..2 = basis * (Xpos - refPos)
__global__ void __launch_bounds__(256, 8) k_transform(const float* __restrict__ x,
                                                      float* __restrict__ out, int T) {
    const int nv = T >> 2;
    const size_t Ts = (size_t)T;
    const float b00 = g_par[0], b01 = g_par[1], b02 = g_par[2];
    const float b10 = g_par[3], b11 = g_par[4], b12 = g_par[5];
    const float b20 = g_par[6], b21 = g_par[7], b22 = g_par[8];
    const float r0 = g_par[9], r1 = g_par[10], r2 = g_par[11];

    const float4* __restrict__ x0 = (const float4*)(x);
    const float4* __restrict__ x1 = (const float4*)(x + Ts);
    const float4* __restrict__ x2 = (const float4*)(x + 2 * Ts);
    float4* __restrict__ o0 = (float4*)(out);
    float4* __restrict__ o1 = (float4*)(out + Ts);
    float4* __restrict__ o2 = (float4*)(out + 2 * Ts);

    const int gid = blockIdx.x * blockDim.x + threadIdx.x;
    const int stride = gridDim.x * blockDim.x;

    for (int i = gid; i < nv; i += stride) {
        float4 v0 = x0[i], v1 = x1[i], v2 = x2[i];
        float c0[4] = {v0.x, v0.y, v0.z, v0.w};
        float c1[4] = {v1.x, v1.y, v1.z, v1.w};
        float c2[4] = {v2.x, v2.y, v2.z, v2.w};
        float w0[4], w1[4], w2[4];
#pragma unroll
        for (int k = 0; k < 4; ++k) {
            float d0 = c0[k] - r0, d1 = c1[k] - r1, d2 = c2[k] - r2;
            w0[k] = b00 * d0 + b01 * d1 + b02 * d2;
            w1[k] = b10 * d0 + b11 * d1 + b12 * d2;
            w2[k] = b20 * d0 + b21 * d1 + b22 * d2;
        }
        o0[i] = make_float4(w0[0], w0[1], w0[2], w0[3]);
        o1[i] = make_float4(w1[0], w1[1], w1[2], w1[3]);
        o2[i] = make_float4(w2[0], w2[1], w2[2], w2[3]);
    }
    for (int t = (nv << 2) + gid; t < T; t += stride) {
        float d0 = x[t] - r0, d1 = x[Ts + t] - r1, d2 = x[2 * Ts + t] - r2;
        out[t]          = b00 * d0 + b01 * d1 + b02 * d2;
        out[Ts + t]     = b10 * d0 + b11 * d1 + b12 * d2;
        out[2 * Ts + t] = b20 * d0 + b21 * d1 + b22 * d2;
    }
}

extern "C" void kernel_launch(void* const* d_in, const int* in_sizes, int n_in,
                              void* d_out, int out_size) {
    const float* x  = (const float*)d_in[0];
    const float* ra = (const float*)d_in[1];
    float* out = (float*)d_out;
    const int T = in_sizes[0] / 10;

    k_reduce<<<RED_NB, 256>>>(x, T);
    k_mid<<<CPY_NB + 1, 256>>>(x, ra, out, T);
    k_transform<<<TRF_NB, 256>>>(x, out, T);
}

// round 6
// speedup vs baseline: 1.1863x; 1.0060x over previous
#include <cuda_runtime.h>

#define MAX_BLOCKS 4736   // 148 SMs x 32 (hard ceiling on resident blocks)
#define SENTINEL   0x7FFFFFFF

// Device-global scratch (no allocations allowed).
static __device__ double g_part[MAX_BLOCKS][9]; // per-block partials
static __device__ float  g_par[12];             // basis rows (right,up,fwd)[9], refPos[3]
static __device__ int    g_cnt1;                // phase-A arrival counter -> SENTINEL when solved
static __device__ int    g_cnt2;                // completion counter (for reset)

__global__ void __launch_bounds__(256) k_fused(const float* __restrict__ x,
                                               const float* __restrict__ ra,
                                               float* __restrict__ out, int T) {
    const int nv = T >> 2;
    const size_t Ts = (size_t)T;
    const int NB = gridDim.x;
    const int tid = threadIdx.x;
    const int gid = blockIdx.x * 256 + tid;
    const int stride = NB * 256;

    // ================= Phase A: covariance partial reduce (rows 0..2) =================
    {
        const float4* __restrict__ x0 = (const float4*)(x);
        const float4* __restrict__ x1 = (const float4*)(x + Ts);
        const float4* __restrict__ x2 = (const float4*)(x + 2 * Ts);
        float acc[9];
#pragma unroll
        for (int k = 0; k < 9; ++k) acc[k] = 0.0f;

        int i = gid;
        for (; i + stride < nv; i += 2 * stride) {
            const int j = i + stride;
            float4 v0 = x0[i], v1 = x1[i], v2 = x2[i];
            float4 u0 = x0[j], u1 = x1[j], u2 = x2[j];
            float c0[8] = {v0.x, v0.y, v0.z, v0.w, u0.x, u0.y, u0.z, u0.w};
            float c1[8] = {v1.x, v1.y, v1.z, v1.w, u1.x, u1.y, u1.z, u1.w};
            float c2[8] = {v2.x, v2.y, v2.z, v2.w, u2.x, u2.y, u2.z, u2.w};
#pragma unroll
            for (int k = 0; k < 8; ++k) {
                float a = c0[k], b = c1[k], c = c2[k];
                acc[0] += a;     acc[1] += b;     acc[2] += c;
                acc[3] += a * a; acc[4] += b * b; acc[5] += c * c;
                acc[6] += a * b; acc[7] += a * c; acc[8] += b * c;
            }
        }
        for (; i < nv; i += stride) {
            float4 v0 = x0[i], v1 = x1[i], v2 = x2[i];
            float c0[4] = {v0.x, v0.y, v0.z, v0.w};
            float c1[4] = {v1.x, v1.y, v1.z, v1.w};
            float c2[4] = {v2.x, v2.y, v2.z, v2.w};
#pragma unroll
            for (int k = 0; k < 4; ++k) {
                float a = c0[k], b = c1[k], c = c2[k];
                acc[0] += a;     acc[1] += b;     acc[2] += c;
                acc[3] += a * a; acc[4] += b * b; acc[5] += c * c;
                acc[6] += a * b; acc[7] += a * c; acc[8] += b * c;
            }
        }
        for (int t = (nv << 2) + gid; t < T; t += stride) {  // scalar tail
            float a = x[t], b = x[Ts + t], c = x[2 * Ts + t];
            acc[0] += a;     acc[1] += b;     acc[2] += c;
            acc[3] += a * a; acc[4] += b * b; acc[5] += c * c;
            acc[6] += a * b; acc[7] += a * c; acc[8] += b * c;
        }

#pragma unroll
        for (int k = 0; k < 9; ++k) {
            float v = acc[k];
#pragma unroll
            for (int off = 16; off > 0; off >>= 1)
                v += __shfl_down_sync(0xffffffffu, v, off);
            acc[k] = v;
        }
        __shared__ float ws[9][8];
        const int lane = tid & 31, warp = tid >> 5;
        if (lane == 0) {
#pragma unroll
            for (int k = 0; k < 9; ++k) ws[k][warp] = acc[k];
        }
        __syncthreads();
        if (tid < 9) {
            double d = 0.0;
#pragma unroll
            for (int w = 0; w < 8; ++w) d += (double)ws[tid][w];
            g_part[blockIdx.x][tid] = d;
        }
    }

    // ---- arrival: last block to arrive becomes the solver ----
    __shared__ int s_rank;
    __threadfence();
    __syncthreads();
    if (tid == 0) s_rank = atomicAdd(&g_cnt1, 1);
    __syncthreads();
    const int rank = s_rank;
    const bool solver = (rank == NB - 1);

    if (solver) {
        // ---- final reduce of g_part (parallel over 256 threads) ----
        double acc[9];
#pragma unroll
        for (int k = 0; k < 9; ++k) acc[k] = 0.0;
        for (int i = tid; i < NB; i += 256) {
#pragma unroll
            for (int k = 0; k < 9; ++k) acc[k] += g_part[i][k];
        }
#pragma unroll
        for (int k = 0; k < 9; ++k) {
            double v = acc[k];
#pragma unroll
            for (int off = 16; off > 0; off >>= 1)
                v += __shfl_down_sync(0xffffffffu, v, off);
            acc[k] = v;
        }
        __shared__ double wd[9][8];
        const int lane = tid & 31, warp = tid >> 5;
        if (lane == 0) {
#pragma unroll
            for (int k = 0; k < 9; ++k) wd[k][warp] = acc[k];
        }
        __syncthreads();
        if (tid == 0) {
            double S[9];
#pragma unroll
            for (int k = 0; k < 9; ++k) {
                double d = 0.0;
#pragma unroll
                for (int w = 0; w < 8; ++w) d += wd[k][w];
                S[k] = d;
            }
            // covariance -> Jacobi (double) -> basis
            const double Tn = (double)T;
            double A[3][3];
            A[0][0] = (S[3] - S[0] * S[0] / Tn) / (Tn - 1.0);
            A[1][1] = (S[4] - S[1] * S[1] / Tn) / (Tn - 1.0);
            A[2][2] = (S[5] - S[2] * S[2] / Tn) / (Tn - 1.0);
            A[0][1] = A[1][0] = (S[6] - S[0] * S[1] / Tn) / (Tn - 1.0);
            A[0][2] = A[2][0] = (S[7] - S[0] * S[2] / Tn) / (Tn - 1.0);
            A[1][2] = A[2][1] = (S[8] - S[1] * S[2] / Tn) / (Tn - 1.0);

            const double scale = fabs(A[0][0]) + fabs(A[1][1]) + fabs(A[2][2]) + 1e-300;
            double V[3][3] = {{1, 0, 0}, {0, 1, 0}, {0, 0, 1}};
            for (int sweep = 0; sweep < 8; ++sweep) {
                double off = fabs(A[0][1]) + fabs(A[0][2]) + fabs(A[1][2]);
                if (off < 1e-14 * scale) break;
                for (int p = 0; p < 2; ++p) {
                    for (int q = p + 1; q < 3; ++q) {
                        double apq = A[p][q];
                        if (fabs(apq) < 1e-200) continue;
                        double theta = (A[q][q] - A[p][p]) / (2.0 * apq);
                        double t = 1.0 / (fabs(theta) + sqrt(theta * theta + 1.0));
                        if (theta < 0.0) t = -t;
                        double c = 1.0 / sqrt(t * t + 1.0);
                        double s = t * c;
                        double app = A[p][p], aqq = A[q][q];
                        A[p][p] = app - t * apq;
                        A[q][q] = aqq + t * apq;
                        A[p][q] = A[q][p] = 0.0;
                        int r = 3 - p - q;
                        double arp = A[r][p], arq = A[r][q];
                        A[r][p] = A[p][r] = c * arp - s * arq;
                        A[r][q] = A[q][r] = s * arp + c * arq;
                        for (int i = 0; i < 3; ++i) {
                            double vip = V[i][p], viq = V[i][q];
                            V[i][p] = c * vip - s * viq;
                            V[i][q] = s * vip + c * viq;
                        }
                    }
                }
            }
            int m = 0;
            if (A[1][1] > A[m][m]) m = 1;
            if (A[2][2] > A[m][m]) m = 2;
            double vz0 = V[0][m], vz1 = V[1][m], vz2 = V[2][m];

            double qx = (double)x[3 * Ts], qy = (double)x[4 * Ts];
            double qz = (double)x[5 * Ts], qw = (double)x[6 * Ts];
            double zfx = 2.0 * (qx * qz + qw * qy);
            double zfy = 2.0 * (qy * qz - qw * qx);
            double zfz = 1.0 - 2.0 * (qx * qx + qy * qy);
            if (zfx * vz0 + zfy * vz1 + zfz * vz2 < 0.0) { vz0 = -vz0; vz1 = -vz1; vz2 = -vz2; }

            double ux = (double)ra[0], uy = (double)ra[1], uz = (double)ra[2];
            double rx = uy * vz2 - uz * vz1;   // right = up x pca_z
            double ry = uz * vz0 - ux * vz2;
            double rz = ux * vz1 - uy * vz0;
            double fx = ry * uz - rz * uy;     // fwd = right x up
            double fy = rz * ux - rx * uz;
            double fz = rx * uy - ry * ux;

            g_par[0] = (float)rx; g_par[1] = (float)ry; g_par[2] = (float)rz;
            g_par[3] = (float)ux; g_par[4] = (float)uy; g_par[5] = (float)uz;
            g_par[6] = (float)fx; g_par[7] = (float)fy; g_par[8] = (float)fz;
            g_par[9]  = x[0];
            g_par[10] = x[Ts];
            g_par[11] = x[2 * Ts];
            __threadfence();
            atomicExch(&g_cnt1, SENTINEL);   // release basis to all blocks
        }
        __syncthreads();
    }

    // ================= Phase B: copy rows 7..9 -> out rows 3..5 =================
    // Partitioned by arrival rank over ALL NB blocks (solver does its share after
    // solving — its slice is 1/NB, negligible). Hides the serial solve.
    {
        const float4* __restrict__ a0 = (const float4*)(x + 7 * Ts);
        const float4* __restrict__ a1 = (const float4*)(x + 8 * Ts);
        const float4* __restrict__ a2 = (const float4*)(x + 9 * Ts);
        float4* __restrict__ o3 = (float4*)(out + 3 * Ts);
        float4* __restrict__ o4 = (float4*)(out + 4 * Ts);
        float4* __restrict__ o5 = (float4*)(out + 5 * Ts);
        const int cg = rank * 256 + tid;
        for (int i = cg; i < nv; i += stride) {
            o3[i] = a0[i];
            o4[i] = a1[i];
            o5[i] = a2[i];
        }
        for (int t = (nv << 2) + cg; t < T; t += stride) {
            out[3 * Ts + t] = x[7 * Ts + t];
            out[4 * Ts + t] = x[8 * Ts + t];
            out[5 * Ts + t] = x[9 * Ts + t];
        }
    }

    // ---- wait for basis ----
    if (tid == 0) {
        while (atomicAdd(&g_cnt1, 0) != SENTINEL) __nanosleep(64);
        __threadfence();
    }
    __syncthreads();

    // ================= Phase C: out rows 0..2 = basis * (Xpos - refPos) =================
    {
        const float b00 = g_par[0], b01 = g_par[1], b02 = g_par[2];
        const float b10 = g_par[3], b11 = g_par[4], b12 = g_par[5];
        const float b20 = g_par[6], b21 = g_par[7], b22 = g_par[8];
        const float r0 = g_par[9], r1 = g_par[10], r2 = g_par[11];

        const float4* __restrict__ x0 = (const float4*)(x);
        const float4* __restrict__ x1 = (const float4*)(x + Ts);
        const float4* __restrict__ x2 = (const float4*)(x + 2 * Ts);
        float4* __restrict__ o0 = (float4*)(out);
        float4* __restrict__ o1 = (float4*)(out + Ts);
        float4* __restrict__ o2 = (float4*)(out + 2 * Ts);

        for (int i = gid; i < nv; i += stride) {
            float4 v0 = x0[i], v1 = x1[i], v2 = x2[i];
            float c0[4] = {v0.x, v0.y, v0.z, v0.w};
            float c1[4] = {v1.x, v1.y, v1.z, v1.w};
            float c2[4] = {v2.x, v2.y, v2.z, v2.w};
            float w0[4], w1[4], w2[4];
#pragma unroll
            for (int k = 0; k < 4; ++k) {
                float d0 = c0[k] - r0, d1 = c1[k] - r1, d2 = c2[k] - r2;
                w0[k] = b00 * d0 + b01 * d1 + b02 * d2;
                w1[k] = b10 * d0 + b11 * d1 + b12 * d2;
                w2[k] = b20 * d0 + b21 * d1 + b22 * d2;
            }
            o0[i] = make_float4(w0[0], w0[1], w0[2], w0[3]);
            o1[i] = make_float4(w1[0], w1[1], w1[2], w1[3]);
            o2[i] = make_float4(w2[0], w2[1], w2[2], w2[3]);
        }
        for (int t = (nv << 2) + gid; t < T; t += stride) {
            float d0 = x[t] - r0, d1 = x[Ts + t] - r1, d2 = x[2 * Ts + t] - r2;
            out[t]          = b00 * d0 + b01 * d1 + b02 * d2;
            out[Ts + t]     = b10 * d0 + b11 * d1 + b12 * d2;
            out[2 * Ts + t] = b20 * d0 + b21 * d1 + b22 * d2;
        }
    }

    // ---- self-reset for next replay (graph-capture safe) ----
    __threadfence();
    __syncthreads();
    if (tid == 0) {
        int done = atomicAdd(&g_cnt2, 1);
        if (done == NB - 1) {
            g_cnt1 = 0;
            g_cnt2 = 0;
            __threadfence();
        }
    }
}

extern "C" void kernel_launch(void* const* d_in, const int* in_sizes, int n_in,
                              void* d_out, int out_size) {
    const float* x  = (const float*)d_in[0];
    const float* ra = (const float*)d_in[1];
    float* out = (float*)d_out;
    const int T = in_sizes[0] / 10;
    const int nv = (T >> 2) > 0 ? (T >> 2) : 1;

    // All blocks MUST be co-resident (spin-sync). Query true occupancy.
    int dev = 0, nsm = 148, occ = 4;
    cudaGetDevice(&dev);
    cudaDeviceGetAttribute(&nsm, cudaDevAttrMultiProcessorCount, dev);
    cudaOccupancyMaxActiveBlocksPerMultiprocessor(&occ, k_fused, 256, 0);
    if (occ < 1) occ = 1;
    long long cap = (long long)nsm * occ;
    if (cap > MAX_BLOCKS) cap = MAX_BLOCKS;
    long long needed = (nv + 255) / 256;
    int blocks = (int)((cap < needed) ? cap : needed);
    if (blocks < 1) blocks = 1;

    k_fused<<<blocks, 256>>>(x, ra, out, T);
}

// round 8
// speedup vs baseline: 1.2880x; 1.0857x over previous
#include <cuda_runtime.h>

#define RED_NB 912    // 6 blocks/SM x 152 SMs — one exact wave for k_reduce
#define TRF_NB 1216   // 8 blocks/SM x 152 SMs — one exact wave for k_out

// Device-global scratch (no allocations allowed).
static __device__ double g_part[RED_NB][9]; // per-block partials
static __device__ float  g_par[12];         // basis rows (right,up,fwd)[9], refPos[3]
static __device__ int    g_cnt;             // arrival counter (self-resetting)

// K1: covariance reduce over rows 0..2; last-arriving block finishes the sum
// and runs the ANALYTIC 3x3 eigensolve (no iterative Jacobi).
__global__ void __launch_bounds__(256, 6) k_reduce(const float* __restrict__ x,
                                                   const float* __restrict__ ra, int T) {
    const int nv = T >> 2;
    const size_t Ts = (size_t)T;
    const int tid = threadIdx.x;
    const int gid = blockIdx.x * 256 + tid;
    const int stride = gridDim.x * 256;
    const int NB = gridDim.x;

    {
        const float4* __restrict__ x0 = (const float4*)(x);
        const float4* __restrict__ x1 = (const float4*)(x + Ts);
        const float4* __restrict__ x2 = (const float4*)(x + 2 * Ts);
        float acc[9];
#pragma unroll
        for (int k = 0; k < 9; ++k) acc[k] = 0.0f;

        int i = gid;
        for (; i + stride < nv; i += 2 * stride) {
            const int j = i + stride;
            float4 v0 = x0[i], v1 = x1[i], v2 = x2[i];
            float4 u0 = x0[j], u1 = x1[j], u2 = x2[j];
            float c0[8] = {v0.x, v0.y, v0.z, v0.w, u0.x, u0.y, u0.z, u0.w};
            float c1[8] = {v1.x, v1.y, v1.z, v1.w, u1.x, u1.y, u1.z, u1.w};
            float c2[8] = {v2.x, v2.y, v2.z, v2.w, u2.x, u2.y, u2.z, u2.w};
#pragma unroll
            for (int k = 0; k < 8; ++k) {
                float a = c0[k], b = c1[k], c = c2[k];
                acc[0] += a;     acc[1] += b;     acc[2] += c;
                acc[3] += a * a; acc[4] += b * b; acc[5] += c * c;
                acc[6] += a * b; acc[7] += a * c; acc[8] += b * c;
            }
        }
        for (; i < nv; i += stride) {
            float4 v0 = x0[i], v1 = x1[i], v2 = x2[i];
            float c0[4] = {v0.x, v0.y, v0.z, v0.w};
            float c1[4] = {v1.x, v1.y, v1.z, v1.w};
            float c2[4] = {v2.x, v2.y, v2.z, v2.w};
#pragma unroll
            for (int k = 0; k < 4; ++k) {
                float a = c0[k], b = c1[k], c = c2[k];
                acc[0] += a;     acc[1] += b;     acc[2] += c;
                acc[3] += a * a; acc[4] += b * b; acc[5] += c * c;
                acc[6] += a * b; acc[7] += a * c; acc[8] += b * c;
            }
        }
        for (int t = (nv << 2) + gid; t < T; t += stride) {  // scalar tail
            float a = x[t], b = x[Ts + t], c = x[2 * Ts + t];
            acc[0] += a;     acc[1] += b;     acc[2] += c;
            acc[3] += a * a; acc[4] += b * b; acc[5] += c * c;
            acc[6] += a * b; acc[7] += a * c; acc[8] += b * c;
        }

#pragma unroll
        for (int k = 0; k < 9; ++k) {
            float v = acc[k];
#pragma unroll
            for (int off = 16; off > 0; off >>= 1)
                v += __shfl_down_sync(0xffffffffu, v, off);
            acc[k] = v;
        }
        __shared__ float ws[9][8];
        const int lane = tid & 31, warp = tid >> 5;
        if (lane == 0) {
#pragma unroll
            for (int k = 0; k < 9; ++k) ws[k][warp] = acc[k];
        }
        __syncthreads();
        if (tid < 9) {
            double d = 0.0;
#pragma unroll
            for (int w = 0; w < 8; ++w) d += (double)ws[tid][w];
            g_part[blockIdx.x][tid] = d;
        }
    }

    // ---- arrival: last block finishes ----
    __shared__ int s_last;
    __threadfence();
    __syncthreads();
    if (tid == 0) s_last = (atomicAdd(&g_cnt, 1) == NB - 1);
    __syncthreads();
    if (!s_last) return;

    // ---- final reduce of g_part (256 threads) ----
    double acc[9];
#pragma unroll
    for (int k = 0; k < 9; ++k) acc[k] = 0.0;
    for (int i = tid; i < NB; i += 256) {
#pragma unroll
        for (int k = 0; k < 9; ++k) acc[k] += g_part[i][k];
    }
#pragma unroll
    for (int k = 0; k < 9; ++k) {
        double v = acc[k];
#pragma unroll
        for (int off = 16; off > 0; off >>= 1)
            v += __shfl_down_sync(0xffffffffu, v, off);
        acc[k] = v;
    }
    __shared__ double wd[9][8];
    const int lane = tid & 31, warp = tid >> 5;
    if (lane == 0) {
#pragma unroll
        for (int k = 0; k < 9; ++k) wd[k][warp] = acc[k];
    }
    __syncthreads();
    if (tid != 0) return;

    double S[9];
#pragma unroll
    for (int k = 0; k < 9; ++k) {
        double d = 0.0;
#pragma unroll
        for (int w = 0; w < 8; ++w) d += wd[k][w];
        S[k] = d;
    }

    // ---- covariance (double) ----
    const double Tn = (double)T;
    double a00 = (S[3] - S[0] * S[0] / Tn) / (Tn - 1.0);
    double a11 = (S[4] - S[1] * S[1] / Tn) / (Tn - 1.0);
    double a22 = (S[5] - S[2] * S[2] / Tn) / (Tn - 1.0);
    double a01 = (S[6] - S[0] * S[1] / Tn) / (Tn - 1.0);
    double a02 = (S[7] - S[0] * S[2] / Tn) / (Tn - 1.0);
    double a12 = (S[8] - S[1] * S[2] / Tn) / (Tn - 1.0);

    // ---- analytic largest eigenvalue (trigonometric method) ----
    double q = (a00 + a11 + a22) / 3.0;
    double b00 = a00 - q, b11 = a11 - q, b22 = a22 - q;
    double p2 = (b00 * b00 + b11 * b11 + b22 * b22
                 + 2.0 * (a01 * a01 + a02 * a02 + a12 * a12)) / 6.0;
    double vz0, vz1, vz2;
    if (p2 <= 0.0) {
        // A is (numerically) a multiple of I: any axis; pick z like eigh would return last.
        vz0 = 0.0; vz1 = 0.0; vz2 = 1.0;
    } else {
        double p = sqrt(p2);
        // r = det(B)/ (2 p^3), B = A - qI
        double detB = b00 * (b11 * b22 - a12 * a12)
                    - a01 * (a01 * b22 - a12 * a02)
                    + a02 * (a01 * a12 - b11 * a02);
        double r = detB / (2.0 * p2 * p);
        if (r > 1.0) r = 1.0;
        if (r < -1.0) r = -1.0;
        double phi = acos(r) / 3.0;
        double lmax = q + 2.0 * p * cos(phi);

        // eigenvector: cross products of rows of (A - lmax I); take the largest
        double m00 = a00 - lmax, m11 = a11 - lmax, m22 = a22 - lmax;
        // rows: (m00,a01,a02), (a01,m11,a12), (a02,a12,m22)
        double c0x = a01 * a12 - m11 * a02;   // r0 x r1
        double c0y = a02 * a01 - m00 * a12;
        double c0z = m00 * m11 - a01 * a01;
        double c1x = a01 * m22 - a12 * a02;   // r0 x r2
        double c1y = a02 * a02 - m00 * m22;
        double c1z = m00 * a12 - a01 * a02;
        double c2x = m11 * m22 - a12 * a12;   // r1 x r2
        double c2y = a12 * a02 - a01 * m22;
        double c2z = a01 * a12 - m11 * a02;
        double n0 = c0x * c0x + c0y * c0y + c0z * c0z;
        double n1 = c1x * c1x + c1y * c1y + c1z * c1z;
        double n2 = c2x * c2x + c2y * c2y + c2z * c2z;
        double vx = c0x, vy = c0y, vz = c0z, nb = n0;
        if (n1 > nb) { vx = c1x; vy = c1y; vz = c1z; nb = n1; }
        if (n2 > nb) { vx = c2x; vy = c2y; vz = c2z; nb = n2; }
        double inv = rsqrt(nb);
        vz0 = vx * inv; vz1 = vy * inv; vz2 = vz * inv;
    }

    // ---- sign fix vs quaternion-forward, then basis ----
    double qx = (double)x[3 * Ts], qy = (double)x[4 * Ts];
    double qz = (double)x[5 * Ts], qw = (double)x[6 * Ts];
    double zfx = 2.0 * (qx * qz + qw * qy);
    double zfy = 2.0 * (qy * qz - qw * qx);
    double zfz = 1.0 - 2.0 * (qx * qx + qy * qy);
    if (zfx * vz0 + zfy * vz1 + zfz * vz2 < 0.0) { vz0 = -vz0; vz1 = -vz1; vz2 = -vz2; }

    double ux = (double)ra[0], uy = (double)ra[1], uz = (double)ra[2];
    double rx = uy * vz2 - uz * vz1;   // right = up x pca_z
    double ry = uz * vz0 - ux * vz2;
    double rz = ux * vz1 - uy * vz0;
    double fx = ry * uz - rz * uy;     // fwd = right x up
    double fy = rz * ux - rx * uz;
    double fz = rx * uy - ry * ux;

    g_par[0] = (float)rx; g_par[1] = (float)ry; g_par[2] = (float)rz;
    g_par[3] = (float)ux; g_par[4] = (float)uy; g_par[5] = (float)uz;
    g_par[6] = (float)fx; g_par[7] = (float)fy; g_par[8] = (float)fz;
    g_par[9]  = x[0];
    g_par[10] = x[Ts];
    g_par[11] = x[2 * Ts];
    g_cnt = 0;   // self-reset for next graph replay
    __threadfence();
}

// K2: fused output pass — rows 0..2 transformed, rows 7..9 copied to out rows 3..5.
__global__ void __launch_bounds__(256, 8) k_out(const float* __restrict__ x,
                                                float* __restrict__ out, int T) {
    const int nv = T >> 2;
    const size_t Ts = (size_t)T;
    const float b00 = g_par[0], b01 = g_par[1], b02 = g_par[2];
    const float b10 = g_par[3], b11 = g_par[4], b12 = g_par[5];
    const float b20 = g_par[6], b21 = g_par[7], b22 = g_par[8];
    const float r0 = g_par[9], r1 = g_par[10], r2 = g_par[11];

    const float4* __restrict__ x0 = (const float4*)(x);
    const float4* __restrict__ x1 = (const float4*)(x + Ts);
    const float4* __restrict__ x2 = (const float4*)(x + 2 * Ts);
    const float4* __restrict__ a0 = (const float4*)(x + 7 * Ts);
    const float4* __restrict__ a1 = (const float4*)(x + 8 * Ts);
    const float4* __restrict__ a2 = (const float4*)(x + 9 * Ts);
    float4* __restrict__ o0 = (float4*)(out);
    float4* __restrict__ o1 = (float4*)(out + Ts);
    float4* __restrict__ o2 = (float4*)(out + 2 * Ts);
    float4* __restrict__ o3 = (float4*)(out + 3 * Ts);
    float4* __restrict__ o4 = (float4*)(out + 4 * Ts);
    float4* __restrict__ o5 = (float4*)(out + 5 * Ts);

    const int gid = blockIdx.x * 256 + threadIdx.x;
    const int stride = gridDim.x * 256;

    for (int i = gid; i < nv; i += stride) {
        float4 v0 = x0[i], v1 = x1[i], v2 = x2[i];
        float4 w3 = a0[i], w4 = a1[i], w5 = a2[i];
        float c0[4] = {v0.x, v0.y, v0.z, v0.w};
        float c1[4] = {v1.x, v1.y, v1.z, v1.w};
        float c2[4] = {v2.x, v2.y, v2.z, v2.w};
        float w0[4], w1[4], w2[4];
#pragma unroll
        for (int k = 0; k < 4; ++k) {
            float d0 = c0[k] - r0, d1 = c1[k] - r1, d2 = c2[k] - r2;
            w0[k] = b00 * d0 + b01 * d1 + b02 * d2;
            w1[k] = b10 * d0 + b11 * d1 + b12 * d2;
            w2[k] = b20 * d0 + b21 * d1 + b22 * d2;
        }
        o0[i] = make_float4(w0[0], w0[1], w0[2], w0[3]);
        o1[i] = make_float4(w1[0], w1[1], w1[2], w1[3]);
        o2[i] = make_float4(w2[0], w2[1], w2[2], w2[3]);
        o3[i] = w3;
        o4[i] = w4;
        o5[i] = w5;
    }
    for (int t = (nv << 2) + gid; t < T; t += stride) {  // scalar tail
        float d0 = x[t] - r0, d1 = x[Ts + t] - r1, d2 = x[2 * Ts + t] - r2;
        out[t]          = b00 * d0 + b01 * d1 + b02 * d2;
        out[Ts + t]     = b10 * d0 + b11 * d1 + b12 * d2;
        out[2 * Ts + t] = b20 * d0 + b21 * d1 + b22 * d2;
        out[3 * Ts + t] = x[7 * Ts + t];
        out[4 * Ts + t] = x[8 * Ts + t];
        out[5 * Ts + t] = x[9 * Ts + t];
    }
}

extern "C" void kernel_launch(void* const* d_in, const int* in_sizes, int n_in,
                              void* d_out, int out_size) {
    const float* x  = (const float*)d_in[0];
    const float* ra = (const float*)d_in[1];
    float* out = (float*)d_out;
    const int T = in_sizes[0] / 10;
    const int nv = (T >> 2) > 0 ? (T >> 2) : 1;

    int rb = RED_NB, tb = TRF_NB;
    int needed = (nv + 255) / 256;
    if (rb > needed) rb = needed;
    if (tb > needed) tb = needed;
    if (rb < 1) rb = 1;
    if (tb < 1) tb = 1;

    k_reduce<<<rb, 256>>>(x, ra, T);
    k_out<<<tb, 256>>>(x, out, T);
}